// round 2
// baseline (speedup 1.0000x reference)
#include <cuda_runtime.h>

// GCN: N=100000, E=1600000, 16 -> 64 -> (128 -> 16 folded)
static constexpr int MAXN = 100000;
static constexpr int MAXE = 1600000;

// Scratch (device globals; no allocation allowed)
__device__ int   g_deg[MAXN];          // edge-only in-degree
__device__ float g_dinv[MAXN];
__device__ int   g_off[MAXN + 1];
__device__ int   g_cur[MAXN];
__device__ int   g_csr[MAXE];
__device__ int   g_bsum[128];
__device__ float g_xs[MAXN * 16];      // dinv-scaled input features
__device__ float g_a1[MAXN * 16];      // aggregated x
__device__ float g_z[MAXN * 16];       // dinv * relu(a1@W1+b1) @ W2L
__device__ float g_w2l[64 * 16];       // W2 @ WL
__device__ float g_b2l[16];            // b2 @ WL + bL

// ---------------------------------------------------------------- degree
__global__ void k_init_deg(int n) {
    int i = blockIdx.x * blockDim.x + threadIdx.x;
    if (i < n) g_deg[i] = 0;
}

__global__ void k_count(const int* __restrict__ ei, int e) {
    int i = blockIdx.x * blockDim.x + threadIdx.x;
    if (i < e) atomicAdd(&g_deg[ei[e + i]], 1);
}

__global__ void k_dinv_xs(const float* __restrict__ x, int n) {
    int i = blockIdx.x * blockDim.x + threadIdx.x;
    if (i >= n) return;
    float d = rsqrtf((float)(g_deg[i] + 1));  // +1 self-loop
    g_dinv[i] = d;
    const float4* xr = (const float4*)(x + (size_t)i * 16);
    float4* o = (float4*)(g_xs + (size_t)i * 16);
#pragma unroll
    for (int r = 0; r < 4; r++) {
        float4 v = __ldg(&xr[r]);
        v.x *= d; v.y *= d; v.z *= d; v.w *= d;
        o[r] = v;
    }
}

// ---------------------------------------------------------------- CSR build (2-level scan)
__global__ void k_scan1(int n) {
    __shared__ int s[1024];
    int t = threadIdx.x, i = blockIdx.x * 1024 + t;
    int v = (i < n) ? g_deg[i] : 0;
    s[t] = v;
    __syncthreads();
    for (int o = 1; o < 1024; o <<= 1) {
        int a = (t >= o) ? s[t - o] : 0;
        __syncthreads();
        s[t] += a;
        __syncthreads();
    }
    if (i < n) g_off[i] = s[t] - v;
    if (t == 1023) g_bsum[blockIdx.x] = s[1023];
}

__global__ void k_scan2(int nb) {
    __shared__ int s[128];
    int t = threadIdx.x;
    int v = (t < nb) ? g_bsum[t] : 0;
    s[t] = v;
    __syncthreads();
    for (int o = 1; o < 128; o <<= 1) {
        int a = (t >= o) ? s[t - o] : 0;
        __syncthreads();
        s[t] += a;
        __syncthreads();
    }
    if (t < nb) g_bsum[t] = s[t] - v;
}

__global__ void k_scan3(int n, int e) {
    int t = threadIdx.x, i = blockIdx.x * 1024 + t;
    if (i < n) {
        int o = g_off[i] + g_bsum[blockIdx.x];
        g_off[i] = o;
        g_cur[i] = o;
    }
    if (i == 0) g_off[n] = e;
}

__global__ void k_fill(const int* __restrict__ ei, int e) {
    int i = blockIdx.x * blockDim.x + threadIdx.x;
    if (i >= e) return;
    int s = ei[i];
    int d = ei[e + i];
    int pos = atomicAdd(&g_cur[d], 1);
    g_csr[pos] = s;
}

// ---------------------------------------------------------------- gather-aggregate (16 floats/node)
// 4 lanes per node, each lane holds one float4 of the feature.
// src array must already carry dinv[src]; result gets dinv[dst] (+ optional bias).
__device__ __forceinline__ void agg16(const float* __restrict__ srcf,
                                      float* __restrict__ dstf,
                                      const float* __restrict__ bias, int n) {
    int tid = blockIdx.x * blockDim.x + threadIdx.x;
    int node = tid >> 2;
    if (node >= n) return;
    int j = tid & 3;
    int st = g_off[node], en = g_off[node + 1];
    const float4* s4 = (const float4*)srcf;
    float4 acc = __ldg(&s4[node * 4 + j]);  // self term
    float4 acc2 = make_float4(0.f, 0.f, 0.f, 0.f);
    int e = st;
    for (; e + 1 < en; e += 2) {
        int s0 = __ldg(&g_csr[e]);
        int s1 = __ldg(&g_csr[e + 1]);
        float4 v0 = __ldg(&s4[s0 * 4 + j]);
        float4 v1 = __ldg(&s4[s1 * 4 + j]);
        acc.x += v0.x; acc.y += v0.y; acc.z += v0.z; acc.w += v0.w;
        acc2.x += v1.x; acc2.y += v1.y; acc2.z += v1.z; acc2.w += v1.w;
    }
    if (e < en) {
        int s0 = __ldg(&g_csr[e]);
        float4 v0 = __ldg(&s4[s0 * 4 + j]);
        acc.x += v0.x; acc.y += v0.y; acc.z += v0.z; acc.w += v0.w;
    }
    float d = __ldg(&g_dinv[node]);
    float4 r;
    r.x = d * (acc.x + acc2.x);
    r.y = d * (acc.y + acc2.y);
    r.z = d * (acc.z + acc2.z);
    r.w = d * (acc.w + acc2.w);
    if (bias) {
        const float4 b = ((const float4*)bias)[j];
        r.x += b.x; r.y += b.y; r.z += b.z; r.w += b.w;
    }
    ((float4*)dstf)[node * 4 + j] = r;
}

__global__ void k_agg1(int n) { agg16(g_xs, g_a1, nullptr, n); }
__global__ void k_agg2(float* __restrict__ out, int n) { agg16(g_z, out, g_b2l, n); }

// ---------------------------------------------------------------- fused MLP:
// z = (dinv * relu(a1 @ W1 + b1)) @ W2L     (h never leaves registers)
// 256 threads, 64 nodes/block, 4 threads per node (16 h-cols each).
__global__ void k_fused_mlp(const float* __restrict__ W1, const float* __restrict__ b1, int n) {
    __shared__ float4 w4[16 * 16];    // W1 [16][64] as [k][c4]
    __shared__ float4 w2l4[64 * 4];   // W2L [64][16] as [k][c4]
    __shared__ float a_s[64 * 17];
    __shared__ float b_s[64];
    int t = threadIdx.x;
    w4[t] = __ldg(&((const float4*)W1)[t]);
    w2l4[t] = ((const float4*)g_w2l)[t];
    if (t < 64) b_s[t] = __ldg(&b1[t]);
    int nb = blockIdx.x * 64;
#pragma unroll
    for (int r = 0; r < 4; r++) {
        int i = t + r * 256;
        int node = nb + (i >> 4);
        float v = (node < n) ? g_a1[(size_t)nb * 16 + i] : 0.f;
        a_s[(i >> 4) * 17 + (i & 15)] = v;
    }
    __syncthreads();
    int nl = t >> 2, q = t & 3;
    int node = nb + nl;
    if (node >= n) return;
    float a[16];
#pragma unroll
    for (int k = 0; k < 16; k++) a[k] = a_s[nl * 17 + k];

    // h cols [q*16, q*16+16)
    float4 acc[4];
#pragma unroll
    for (int j = 0; j < 4; j++) {
        int c = q * 16 + j * 4;
        acc[j] = make_float4(b_s[c], b_s[c + 1], b_s[c + 2], b_s[c + 3]);
    }
#pragma unroll
    for (int k = 0; k < 16; k++) {
        float av = a[k];
#pragma unroll
        for (int j = 0; j < 4; j++) {
            float4 w = w4[k * 16 + q * 4 + j];
            acc[j].x += av * w.x; acc[j].y += av * w.y;
            acc[j].z += av * w.z; acc[j].w += av * w.w;
        }
    }
    float d = g_dinv[node];

    // partial z = (d * relu(h_q)) @ W2L[q*16 .. q*16+16)
    float4 pz[4];
#pragma unroll
    for (int c = 0; c < 4; c++) pz[c] = make_float4(0.f, 0.f, 0.f, 0.f);
#pragma unroll
    for (int j = 0; j < 4; j++) {
        float hv[4];
        hv[0] = d * fmaxf(acc[j].x, 0.f);
        hv[1] = d * fmaxf(acc[j].y, 0.f);
        hv[2] = d * fmaxf(acc[j].z, 0.f);
        hv[3] = d * fmaxf(acc[j].w, 0.f);
#pragma unroll
        for (int m = 0; m < 4; m++) {
            int k = q * 16 + j * 4 + m;
            float h = hv[m];
#pragma unroll
            for (int c = 0; c < 4; c++) {
                float4 w = w2l4[k * 4 + c];
                pz[c].x += h * w.x; pz[c].y += h * w.y;
                pz[c].z += h * w.z; pz[c].w += h * w.w;
            }
        }
    }
    // butterfly-reduce partial z across the 4 threads of this node
#pragma unroll
    for (int o = 1; o <= 2; o <<= 1) {
#pragma unroll
        for (int c = 0; c < 4; c++) {
            pz[c].x += __shfl_xor_sync(0xffffffffu, pz[c].x, o);
            pz[c].y += __shfl_xor_sync(0xffffffffu, pz[c].y, o);
            pz[c].z += __shfl_xor_sync(0xffffffffu, pz[c].z, o);
            pz[c].w += __shfl_xor_sync(0xffffffffu, pz[c].w, o);
        }
    }
    // every lane holds the full z[16]; lane q writes quarter q
    ((float4*)g_z)[node * 4 + q] = pz[q];
}

// ---------------------------------------------------------------- fold trailing linears
__global__ void k_w2l(const float* __restrict__ W2, const float* __restrict__ b2,
                      const float* __restrict__ WL, const float* __restrict__ bL) {
    int t = threadIdx.x;  // 1024 threads
    int k = t >> 4, c = t & 15;
    float s = 0.f;
    for (int j = 0; j < 128; j++)
        s += __ldg(&W2[k * 128 + j]) * __ldg(&WL[j * 16 + c]);
    g_w2l[t] = s;
    if (t < 16) {
        float sb = __ldg(&bL[t]);
        for (int j = 0; j < 128; j++)
            sb += __ldg(&b2[j]) * __ldg(&WL[j * 16 + t]);
        g_b2l[t] = sb;
    }
}

// ----------------------------------------------------------------
extern "C" void kernel_launch(void* const* d_in, const int* in_sizes, int n_in,
                              void* d_out, int out_size) {
    const float* x  = (const float*)d_in[0];
    const int*   ei = (const int*)d_in[1];
    const float* W1 = (const float*)d_in[2];
    const float* b1 = (const float*)d_in[3];
    const float* W2 = (const float*)d_in[4];
    const float* b2 = (const float*)d_in[5];
    const float* WL = (const float*)d_in[6];
    const float* bL = (const float*)d_in[7];
    float* out = (float*)d_out;

    int n = in_sizes[0] / 16;   // 100000
    int e = in_sizes[1] / 2;    // 1600000
    int nb1024 = (n + 1023) / 1024;

    k_w2l<<<1, 1024>>>(W2, b2, WL, bL);
    k_init_deg<<<(n + 255) / 256, 256>>>(n);
    k_count<<<(e + 255) / 256, 256>>>(ei, e);
    k_dinv_xs<<<(n + 255) / 256, 256>>>(x, n);
    k_scan1<<<nb1024, 1024>>>(n);
    k_scan2<<<1, 128>>>(nb1024);
    k_scan3<<<nb1024, 1024>>>(n, e);
    k_fill<<<(e + 255) / 256, 256>>>(ei, e);
    k_agg1<<<(n * 4 + 255) / 256, 256>>>(n);
    k_fused_mlp<<<(n + 63) / 64, 256>>>(W1, b1, n);
    k_agg2<<<(n * 4 + 255) / 256, 256>>>(out, n);
}

// round 3
// speedup vs baseline: 1.3184x; 1.3184x over previous
#include <cuda_runtime.h>

// GCN: N=100000, E=1600000, 16 -> 64 -> (128 -> 16 folded), single persistent kernel.
static constexpr int MAXN = 100000;
static constexpr int MAXE = 1600000;
static constexpr int NB = 148;     // resident blocks (<= SM count)
static constexpr int NT = 1024;

__device__ int   g_deg[MAXN];
__device__ float g_dinv[MAXN];
__device__ int   g_off[MAXN + 1];
__device__ int   g_cur[MAXN];
__device__ int   g_csr[MAXE];
__device__ int   g_bsum[NB];
__device__ float g_xs[MAXN * 16];
__device__ float g_a1[MAXN * 16];
__device__ float g_z[MAXN * 16];
__device__ float g_w2l[64 * 16];
__device__ float g_b2l[16];
__device__ unsigned g_bar_count;
__device__ unsigned g_bar_gen;

// ---- software grid barrier (all NB blocks resident) ----
__device__ __forceinline__ void gsync() {
    __syncthreads();
    __threadfence();
    if (threadIdx.x == 0) {
        volatile unsigned* genp = &g_bar_gen;
        unsigned gen = *genp;
        if (atomicAdd(&g_bar_count, 1u) == (unsigned)(NB - 1)) {
            g_bar_count = 0;
            __threadfence();
            *genp = gen + 1;
        } else {
            while (*genp == gen) { }
        }
    }
    __syncthreads();
}

// one work item = (node, quarter): gather-sum 4 floats over CSR neighbors
__device__ __forceinline__ void agg16_item(const float* __restrict__ srcf,
                                           float* __restrict__ dstf,
                                           const float* __restrict__ bias, int w) {
    int node = w >> 2;
    int j = w & 3;
    int st = g_off[node], en = g_off[node + 1];
    const float4* s4 = (const float4*)srcf;
    float4 acc = __ldg(&s4[node * 4 + j]);   // self term (src already dinv-scaled)
    float4 acc2 = make_float4(0.f, 0.f, 0.f, 0.f);
    int e = st;
    for (; e + 1 < en; e += 2) {
        int s0 = __ldg(&g_csr[e]);
        int s1 = __ldg(&g_csr[e + 1]);
        float4 v0 = __ldg(&s4[s0 * 4 + j]);
        float4 v1 = __ldg(&s4[s1 * 4 + j]);
        acc.x += v0.x; acc.y += v0.y; acc.z += v0.z; acc.w += v0.w;
        acc2.x += v1.x; acc2.y += v1.y; acc2.z += v1.z; acc2.w += v1.w;
    }
    if (e < en) {
        int s0 = __ldg(&g_csr[e]);
        float4 v0 = __ldg(&s4[s0 * 4 + j]);
        acc.x += v0.x; acc.y += v0.y; acc.z += v0.z; acc.w += v0.w;
    }
    float d = __ldg(&g_dinv[node]);
    float4 r;
    r.x = d * (acc.x + acc2.x);
    r.y = d * (acc.y + acc2.y);
    r.z = d * (acc.z + acc2.z);
    r.w = d * (acc.w + acc2.w);
    if (bias) {
        float4 b = __ldg(&((const float4*)bias)[j]);
        r.x += b.x; r.y += b.y; r.z += b.z; r.w += b.w;
    }
    ((float4*)dstf)[node * 4 + j] = r;
}

__global__ void __launch_bounds__(NT, 1) uber(
    const float* __restrict__ x, const int* __restrict__ ei,
    const float* __restrict__ W1, const float* __restrict__ b1,
    const float* __restrict__ W2, const float* __restrict__ b2,
    const float* __restrict__ WL, const float* __restrict__ bL,
    float* __restrict__ out, int n, int e)
{
    __shared__ float4 sm4[528];   // union: scan ints / MLP weights
    int* si = (int*)sm4;
    const int t = threadIdx.x;
    const int bid = blockIdx.x;
    const int gtid = bid * NT + t;
    const int GSZ = NB * NT;

    // ---- P0: zero degrees; block 0 folds W2@WL, b2@WL+bL ----
    for (int i = gtid; i < n; i += GSZ) g_deg[i] = 0;
    if (bid == 0) {
        int k = t >> 4, c = t & 15;
        float s = 0.f;
        for (int j = 0; j < 128; j++) s += __ldg(&W2[k * 128 + j]) * __ldg(&WL[j * 16 + c]);
        g_w2l[t] = s;
        if (t < 16) {
            float sb = __ldg(&bL[t]);
            for (int j = 0; j < 128; j++) sb += __ldg(&b2[j]) * __ldg(&WL[j * 16 + t]);
            g_b2l[t] = sb;
        }
    }
    gsync();

    // ---- P1: in-degree count ----
    for (int i = gtid; i < e; i += GSZ) atomicAdd(&g_deg[ei[e + i]], 1);
    gsync();

    // ---- P2: dinv + scaled features; block-local scan of degrees ----
    int myDeg = (gtid < n) ? g_deg[gtid] : 0;
    if (gtid < n) {
        float d = rsqrtf((float)(myDeg + 1));   // +1 self-loop
        g_dinv[gtid] = d;
        const float4* xr = (const float4*)(x + (size_t)gtid * 16);
        float4* o = (float4*)(g_xs + (size_t)gtid * 16);
#pragma unroll
        for (int r = 0; r < 4; r++) {
            float4 v = __ldg(&xr[r]);
            v.x *= d; v.y *= d; v.z *= d; v.w *= d;
            o[r] = v;
        }
    }
    si[t] = myDeg;
    __syncthreads();
    for (int o = 1; o < NT; o <<= 1) {
        int a = (t >= o) ? si[t - o] : 0;
        __syncthreads();
        si[t] += a;
        __syncthreads();
    }
    int excl = si[t] - myDeg;          // block-local exclusive prefix
    int btot = si[NT - 1];
    if (t == 0) g_bsum[bid] = btot;
    gsync();

    // ---- P3: block offset = sum of prior block totals; write g_off/g_cur ----
    si[t] = (t < bid) ? g_bsum[t] : 0;
    __syncthreads();
    for (int o2 = 512; o2 > 0; o2 >>= 1) {
        if (t < o2) si[t] += si[t + o2];
        __syncthreads();
    }
    int boff = si[0];
    if (gtid < n) {
        int off = excl + boff;
        g_off[gtid] = off;
        g_cur[gtid] = off;
    }
    if (gtid == 0) g_off[n] = e;
    gsync();

    // ---- P4: CSR fill ----
    for (int i = gtid; i < e; i += GSZ) {
        int s = ei[i];
        int d = ei[e + i];
        g_csr[atomicAdd(&g_cur[d], 1)] = s;
    }
    gsync();

    // ---- P5: layer-1 aggregation (16 floats/node) ----
    for (int w = gtid; w < n * 4; w += GSZ) agg16_item(g_xs, g_a1, nullptr, w);
    gsync();

    // ---- P6: fused MLP  z = (dinv * relu(a1@W1 + b1)) @ W2L ----
    {
        float4* w1t  = sm4;         // [16][16] : W1 row k, col-quad cq
        float4* w2l4 = sm4 + 256;   // [64][4]  : W2L row k, col-quad j
        float4* b1q  = sm4 + 512;   // [16]
        if (t < 256)      w1t[t]        = __ldg(&((const float4*)W1)[t]);
        else if (t < 512) w2l4[t - 256] = ((const float4*)g_w2l)[t - 256];
        else if (t < 528) b1q[t - 512]  = ((const float4*)b1)[t - 512];
        __syncthreads();
        if (gtid < n) {
            const float4* a4 = (const float4*)(g_a1 + (size_t)gtid * 16);
            float a[16];
#pragma unroll
            for (int r = 0; r < 4; r++) {
                float4 v = a4[r];
                a[r * 4 + 0] = v.x; a[r * 4 + 1] = v.y; a[r * 4 + 2] = v.z; a[r * 4 + 3] = v.w;
            }
            float d = g_dinv[gtid];
            float4 z4[4];
#pragma unroll
            for (int j = 0; j < 4; j++) z4[j] = make_float4(0.f, 0.f, 0.f, 0.f);
#pragma unroll
            for (int cq = 0; cq < 16; cq++) {
                float4 h = b1q[cq];
#pragma unroll
                for (int k = 0; k < 16; k++) {
                    float4 w = w1t[k * 16 + cq];
                    float av = a[k];
                    h.x += av * w.x; h.y += av * w.y; h.z += av * w.z; h.w += av * w.w;
                }
                h.x = d * fmaxf(h.x, 0.f);
                h.y = d * fmaxf(h.y, 0.f);
                h.z = d * fmaxf(h.z, 0.f);
                h.w = d * fmaxf(h.w, 0.f);
                int c0 = cq * 4;
                float hv[4] = {h.x, h.y, h.z, h.w};
#pragma unroll
                for (int m = 0; m < 4; m++) {
                    float hm = hv[m];
#pragma unroll
                    for (int j = 0; j < 4; j++) {
                        float4 w = w2l4[(c0 + m) * 4 + j];
                        z4[j].x += hm * w.x; z4[j].y += hm * w.y;
                        z4[j].z += hm * w.z; z4[j].w += hm * w.w;
                    }
                }
            }
            float4* zo = (float4*)(g_z + (size_t)gtid * 16);
#pragma unroll
            for (int j = 0; j < 4; j++) zo[j] = z4[j];
        }
    }
    gsync();

    // ---- P7: layer-2 aggregation + bias -> out ----
    for (int w = gtid; w < n * 4; w += GSZ) agg16_item(g_z, out, g_b2l, w);
}

// ----------------------------------------------------------------
extern "C" void kernel_launch(void* const* d_in, const int* in_sizes, int n_in,
                              void* d_out, int out_size) {
    const float* x  = (const float*)d_in[0];
    const int*   ei = (const int*)d_in[1];
    const float* W1 = (const float*)d_in[2];
    const float* b1 = (const float*)d_in[3];
    const float* W2 = (const float*)d_in[4];
    const float* b2 = (const float*)d_in[5];
    const float* WL = (const float*)d_in[6];
    const float* bL = (const float*)d_in[7];
    float* out = (float*)d_out;

    int n = in_sizes[0] / 16;   // 100000
    int e = in_sizes[1] / 2;    // 1600000

    uber<<<NB, NT>>>(x, ei, W1, b1, W2, b2, WL, bL, out, n, e);
}